// round 11
// baseline (speedup 1.0000x reference)
#include <cuda_runtime.h>

// Problem constants
#define GRID_M     96
#define NUM_NODES  9216          // 96*96
#define MAX_EDGES  36864         // 4*NUM_NODES
#define IMG_W      192
#define MASK_ELEMS 84934656      // 9216*9216
#define NBLK       36            // 9216 / 256 blocks; all co-resident (<=148 SMs)

// Scratch (no allocations). Partials/counts fully rewritten every call.
// Arrive-counters rotate 0 -> 36 -> 0 per call via the reset choreography.
__device__ float g_pmin[NBLK];
__device__ float g_pmax[NBLK];
__device__ int   g_cnt[NBLK];
__device__ int   g_done1;        // init 0
__device__ int   g_done2;        // init 0

// Arrive: release-fence + one atomicAdd. Wait: plain volatile polling (no
// atomic-ALU serialization), then acquire-fence. All NBLK blocks co-resident.
__device__ __forceinline__ void arrive_wait(int* ctr) {
    __syncthreads();
    if (threadIdx.x == 0) {
        __threadfence();
        atomicAdd(ctr, 1);
        volatile int* vc = (volatile int*)ctr;
        while (*vc < NBLK) { }
        __threadfence();
    }
    __syncthreads();
}

// pool+noise value of node (i,j): bit-identical everywhere (same op order).
__device__ __forceinline__ float node_d(const float* __restrict__ dc,
                                        const float* __restrict__ noise,
                                        int i, int j) {
    const float2* r0 = reinterpret_cast<const float2*>(dc + (2 * i) * IMG_W);
    const float2* r1 = reinterpret_cast<const float2*>(dc + (2 * i + 1) * IMG_W);
    float2 a = r0[j];
    float2 c = r1[j];
    return fmaxf(fmaxf(a.x, a.y), fmaxf(c.x, c.y)) + noise[i * GRID_M + j];
}

// --------------------------------------------------------------------------
// Single fused kernel: 36 blocks x 256 threads, one node per thread.
// All global loads are issued before the first wait (independent of barriers).
// --------------------------------------------------------------------------
__global__ __launch_bounds__(256, 1)
void k_fused(const float* __restrict__ dc, const float* __restrict__ noise,
             const unsigned int* __restrict__ mask, float* __restrict__ out) {
    __shared__ float smn[8], smx[8];
    __shared__ float s_th;
    __shared__ int   sws[8];
    __shared__ int   s_base;

    const int b    = blockIdx.x;
    const int t    = threadIdx.x;
    const int lane = t & 31;
    const int w    = t >> 5;
    const int l    = b * 256 + t;          // node id, 0..9215
    const int i    = l / GRID_M;
    const int j    = l - i * GRID_M;

    // Reset counter2 (left at NBLK by previous call). Visible to all before
    // any block arrives there: they must first pass wait-1, which needs block
    // 0's fenced arrival, which program-order-follows this exch.
    if (b == 0 && t == 0) atomicExch(&g_done2, 0);

    // ---- Issue ALL independent loads up front ----
    const bool up    = (i > 0), dn = (i < GRID_M - 1);
    const bool lt    = (j > 0), rt = (j < GRID_M - 1);
    const unsigned rowbase = (unsigned)l * (unsigned)NUM_NODES;

    unsigned mk0 = 0, mk1 = 0, mk2 = 0, mk3 = 0;   // dropout words (0/1)
    if (up && lt) mk0 = mask[rowbase + (unsigned)(l - 97)];
    if (up && rt) mk1 = mask[rowbase + (unsigned)(l - 95)];
    if (dn && lt) mk2 = mask[rowbase + (unsigned)(l + 95)];
    if (dn && rt) mk3 = mask[rowbase + (unsigned)(l + 97)];

    // own pooled value (pre-noise) + d
    float v;
    {
        const float2* r0 = reinterpret_cast<const float2*>(dc + (2 * i) * IMG_W);
        const float2* r1 = reinterpret_cast<const float2*>(dc + (2 * i + 1) * IMG_W);
        float2 a = r0[j];
        float2 c = r1[j];
        v = fmaxf(fmaxf(a.x, a.y), fmaxf(c.x, c.y));
    }
    const float dv = v + noise[l];

    // neighbor d values, recomputed locally (bit-identical to owners')
    float n0 = 0.f, n1 = 0.f, n2 = 0.f, n3 = 0.f;
    if (up && lt) n0 = node_d(dc, noise, i - 1, j - 1);
    if (up && rt) n1 = node_d(dc, noise, i - 1, j + 1);
    if (dn && lt) n2 = node_d(dc, noise, i + 1, j - 1);
    if (dn && rt) n3 = node_d(dc, noise, i + 1, j + 1);

    // ---- Sentinel fill (73728 floats = 2 x float4 per thread) ----
    {
        float4 s4 = make_float4((float)NUM_NODES, (float)NUM_NODES,
                                (float)NUM_NODES, (float)NUM_NODES);
        float4* o4 = reinterpret_cast<float4*>(out);
        o4[l]             = s4;
        o4[l + NUM_NODES] = s4;
    }

    // ---- Block min/max of pooled values -> publish partials ----
    {
        float mn = v, mx = v;
#pragma unroll
        for (int o = 16; o; o >>= 1) {
            mn = fminf(mn, __shfl_xor_sync(0xffffffffu, mn, o));
            mx = fmaxf(mx, __shfl_xor_sync(0xffffffffu, mx, o));
        }
        if (lane == 0) { smn[w] = mn; smx[w] = mx; }
        __syncthreads();
        if (w == 0) {
            mn = smn[lane & 7]; mx = smx[lane & 7];
#pragma unroll
            for (int o = 4; o; o >>= 1) {
                mn = fminf(mn, __shfl_xor_sync(0xffffffffu, mn, o));
                mx = fmaxf(mx, __shfl_xor_sync(0xffffffffu, mx, o));
            }
            if (lane == 0) { g_pmin[b] = mn; g_pmax[b] = mx; }
        }
    }

    arrive_wait(&g_done1);   // partials visible chip-wide

    // ---- Threshold (redundant per block) ----
    if (w == 0) {
        float mn = 3.4e38f, mx = -3.4e38f;
        if (lane < NBLK)      { mn = __ldcg(&g_pmin[lane]);
                                mx = __ldcg(&g_pmax[lane]); }
        if (lane + 32 < NBLK) { mn = fminf(mn, __ldcg(&g_pmin[lane + 32]));
                                mx = fmaxf(mx, __ldcg(&g_pmax[lane + 32])); }
#pragma unroll
        for (int o = 16; o; o >>= 1) {
            mn = fminf(mn, __shfl_xor_sync(0xffffffffu, mn, o));
            mx = fmaxf(mx, __shfl_xor_sync(0xffffffffu, mx, o));
        }
        if (lane == 0) s_th = (mx - mn) / 96.0f;  // exact f32 order as reference
    }
    __syncthreads();
    const float th = s_th;

    // ---- Edge tests (all operands already in registers) ----
    unsigned m = 0;
    if (mk0 && fabsf(n0 - dv) <= th) m |= 1u;   // (i-1,j-1)
    if (mk1 && fabsf(n1 - dv) <= th) m |= 2u;   // (i-1,j+1)
    if (mk2 && fabsf(n2 - dv) <= th) m |= 4u;   // (i+1,j-1)
    if (mk3 && fabsf(n3 - dv) <= th) m |= 8u;   // (i+1,j+1)

    // ---- Block exclusive scan + total ----
    const int c = __popc(m);
    int incl = c;
#pragma unroll
    for (int o = 1; o < 32; o <<= 1) {
        int u = __shfl_up_sync(0xffffffffu, incl, o);
        if (lane >= o) incl += u;
    }
    if (lane == 31) sws[w] = incl;
    __syncthreads();
    int wbase = 0, total = 0;
#pragma unroll
    for (int k = 0; k < 8; k++) {
        int sv = sws[k];
        wbase += (k < w) ? sv : 0;
        total += sv;
    }
    if (t == 0) g_cnt[b] = total;
    const int excl = wbase + (incl - c);

    arrive_wait(&g_done2);   // counts visible chip-wide

    // ---- Global base offset + scatter (jnp.nonzero order) ----
    if (w == 0) {
        int s = (lane < b) ? __ldcg(&g_cnt[lane]) : 0;
        s    += (lane + 32 < b) ? __ldcg(&g_cnt[lane + 32]) : 0;
#pragma unroll
        for (int o = 16; o; o >>= 1) s += __shfl_xor_sync(0xffffffffu, s, o);
        if (lane == 0) s_base = s;
    }
    __syncthreads();

    int pos = s_base + excl;
    const float fl = (float)l;
    if (m & 1u) { out[pos] = fl; out[MAX_EDGES + pos] = (float)(l - 97); pos++; }
    if (m & 2u) { out[pos] = fl; out[MAX_EDGES + pos] = (float)(l - 95); pos++; }
    if (m & 4u) { out[pos] = fl; out[MAX_EDGES + pos] = (float)(l + 95); pos++; }
    if (m & 8u) { out[pos] = fl; out[MAX_EDGES + pos] = (float)(l + 97); pos++; }

    // Reset counter1 for next call (all blocks provably past wait-1).
    if (b == 0 && t == 0) atomicExch(&g_done1, 0);
}

// --------------------------------------------------------------------------
extern "C" void kernel_launch(void* const* d_in, const int* in_sizes, int n_in,
                              void* d_out, int out_size) {
    // Resolve inputs by element count (unique per input):
    //   d_coarse = 36864 (f32), noise = 9216 (f32),
    //   dropout_mask = 84934656 (bool materialized as 4-byte 0/1 words),
    //   R_scale = 1 (unused)
    const float*        dc    = nullptr;
    const float*        noise = nullptr;
    const unsigned int* mask  = nullptr;

    for (int i = 0; i < n_in; i++) {
        int s = in_sizes[i];
        if (s == MASK_ELEMS) mask  = (const unsigned int*)d_in[i];
        else if (s == 36864) dc    = (const float*)d_in[i];
        else if (s == 9216)  noise = (const float*)d_in[i];
    }

    float* out = (float*)d_out;   // [2, 36864] compared as float32

    k_fused<<<NBLK, 256>>>(dc, noise, mask, out);
}

// round 12
// speedup vs baseline: 1.2286x; 1.2286x over previous
#include <cuda_runtime.h>

// Problem constants
#define GRID_M     96
#define NUM_NODES  9216          // 96*96
#define MAX_EDGES  36864         // 4*NUM_NODES
#define IMG_W      192
#define MASK_ELEMS 84934656      // 9216*9216
#define NBLK       36            // 9216 / 256 blocks; all co-resident (<=148 SMs)

// Scratch (no allocations). g_cnt fully rewritten every call before reads.
// g_ticket is a MONOTONIC barrier counter: arrivals take tickets; each call's
// 36 arrivals occupy [36k, 36k+36); waiters poll for >= 36k+36. No reset
// needed, deterministic work every call, overflow after ~59M calls.
__device__ int g_cnt[NBLK];
__device__ int g_ticket;         // init 0

// pool+noise value of node (i,j): bit-identical everywhere (same op order).
__device__ __forceinline__ float node_d(const float* __restrict__ dc,
                                        const float* __restrict__ noise,
                                        int i, int j) {
    const float2* r0 = reinterpret_cast<const float2*>(dc + (2 * i) * IMG_W);
    const float2* r1 = reinterpret_cast<const float2*>(dc + (2 * i + 1) * IMG_W);
    float2 a = r0[j];
    float2 c = r1[j];
    return fmaxf(fmaxf(a.x, a.y), fmaxf(c.x, c.y)) + noise[i * GRID_M + j];
}

// --------------------------------------------------------------------------
// Single fused kernel, ONE grid barrier: 36 blocks x 256 threads, 1 node/thread.
//   - all scattered mask loads + stencil loads issued at cycle 0
//   - threshold computed REDUNDANTLY per block (full 147KB image scan, L2
//     broadcast) -> no barrier needed for min/max
//   - one ticket barrier publishes the 36 per-block edge counts
//   - prefix + scatter in jnp.nonzero order over pre-written sentinels
// --------------------------------------------------------------------------
__global__ __launch_bounds__(256, 1)
void k_fused(const float* __restrict__ dc, const float* __restrict__ noise,
             const unsigned int* __restrict__ mask, float* __restrict__ out) {
    __shared__ float smn[8], smx[8];
    __shared__ int   sws[8];
    __shared__ int   s_base;

    const int b    = blockIdx.x;
    const int t    = threadIdx.x;
    const int lane = t & 31;
    const int w    = t >> 5;
    const int l    = b * 256 + t;          // node id, 0..9215
    const int i    = l / GRID_M;
    const int j    = l - i * GRID_M;

    // ---- Issue ALL independent scattered loads up front ----
    const bool up = (i > 0), dn = (i < GRID_M - 1);
    const bool lt = (j > 0), rt = (j < GRID_M - 1);
    const unsigned rowbase = (unsigned)l * (unsigned)NUM_NODES;

    unsigned mk0 = 0, mk1 = 0, mk2 = 0, mk3 = 0;   // dropout words (0/1)
    if (up && lt) mk0 = mask[rowbase + (unsigned)(l - 97)];
    if (up && rt) mk1 = mask[rowbase + (unsigned)(l - 95)];
    if (dn && lt) mk2 = mask[rowbase + (unsigned)(l + 95)];
    if (dn && rt) mk3 = mask[rowbase + (unsigned)(l + 97)];

    // own d and neighbor d values (bit-identical recomputation)
    const float dv = node_d(dc, noise, i, j);
    float n0 = 0.f, n1 = 0.f, n2 = 0.f, n3 = 0.f;
    if (up && lt) n0 = node_d(dc, noise, i - 1, j - 1);
    if (up && rt) n1 = node_d(dc, noise, i - 1, j + 1);
    if (dn && lt) n2 = node_d(dc, noise, i + 1, j - 1);
    if (dn && rt) n3 = node_d(dc, noise, i + 1, j + 1);

    // ---- Sentinel fill (73728 floats = 2 x float4 per thread) ----
    {
        float4 s4 = make_float4((float)NUM_NODES, (float)NUM_NODES,
                                (float)NUM_NODES, (float)NUM_NODES);
        float4* o4 = reinterpret_cast<float4*>(out);
        o4[l]             = s4;
        o4[l + NUM_NODES] = s4;
    }

    // ---- Redundant global pooled min/max (full image scan per block) ----
    // (i_row, q) pairs: 96 pooled rows x 48 float4-columns = 4608 pairs.
    // Each pair: two float4 loads (dc rows 2i, 2i+1) -> two pooled values.
    float mn = 3.4e38f, mx = -3.4e38f;
#pragma unroll
    for (int k = 0; k < 18; k++) {
        int idx = k * 256 + t;             // 0..4607
        int pi  = idx / 48;
        int q   = idx - pi * 48;
        const float4* r0 = reinterpret_cast<const float4*>(dc + (2 * pi) * IMG_W);
        const float4* r1 = reinterpret_cast<const float4*>(dc + (2 * pi + 1) * IMG_W);
        float4 a = r0[q];
        float4 c = r1[q];
        float pA = fmaxf(fmaxf(a.x, a.y), fmaxf(c.x, c.y));  // pooled (pi, 2q)
        float pB = fmaxf(fmaxf(a.z, a.w), fmaxf(c.z, c.w));  // pooled (pi, 2q+1)
        mn = fminf(mn, fminf(pA, pB));
        mx = fmaxf(mx, fmaxf(pA, pB));
    }
#pragma unroll
    for (int o = 16; o; o >>= 1) {
        mn = fminf(mn, __shfl_xor_sync(0xffffffffu, mn, o));
        mx = fmaxf(mx, __shfl_xor_sync(0xffffffffu, mx, o));
    }
    if (lane == 0) { smn[w] = mn; smx[w] = mx; }
    __syncthreads();
    // every thread reduces the 8 per-warp partials itself (no 2nd sync)
    mn = smn[0]; mx = smx[0];
#pragma unroll
    for (int k = 1; k < 8; k++) {
        mn = fminf(mn, smn[k]);
        mx = fmaxf(mx, smx[k]);
    }
    const float th = (mx - mn) / 96.0f;    // exact f32 op order as reference

    // ---- Edge tests (all operands already in registers) ----
    unsigned m = 0;
    if (mk0 && fabsf(n0 - dv) <= th) m |= 1u;   // (i-1,j-1)
    if (mk1 && fabsf(n1 - dv) <= th) m |= 2u;   // (i-1,j+1)
    if (mk2 && fabsf(n2 - dv) <= th) m |= 4u;   // (i+1,j-1)
    if (mk3 && fabsf(n3 - dv) <= th) m |= 8u;   // (i+1,j+1)

    // ---- Block exclusive scan + total ----
    const int c = __popc(m);
    int incl = c;
#pragma unroll
    for (int o = 1; o < 32; o <<= 1) {
        int u = __shfl_up_sync(0xffffffffu, incl, o);
        if (lane >= o) incl += u;
    }
    if (lane == 31) sws[w] = incl;
    __syncthreads();
    int wbase = 0, total = 0;
#pragma unroll
    for (int k = 0; k < 8; k++) {
        int sv = sws[k];
        wbase += (k < w) ? sv : 0;
        total += sv;
    }
    const int excl = wbase + (incl - c);

    // ---- Ticket grid barrier: publish g_cnt[b], wait for all 36 ----
    if (t == 0) {
        g_cnt[b] = total;
        __threadfence();                   // publish count before arrival
        int old    = atomicAdd(&g_ticket, 1);
        int target = (old / NBLK) * NBLK + NBLK;   // this call's completion mark
        volatile int* vt = (volatile int*)&g_ticket;
        while (*vt < target) { }
        __threadfence();                   // acquire all 36 counts
    }
    __syncthreads();

    // ---- Global base offset + scatter (jnp.nonzero order) ----
    if (w == 0) {
        int s = (lane < b) ? __ldcg(&g_cnt[lane]) : 0;
        s    += (lane + 32 < b) ? __ldcg(&g_cnt[lane + 32]) : 0;
#pragma unroll
        for (int o = 16; o; o >>= 1) s += __shfl_xor_sync(0xffffffffu, s, o);
        if (lane == 0) s_base = s;
    }
    __syncthreads();

    int pos = s_base + excl;
    const float fl = (float)l;
    if (m & 1u) { out[pos] = fl; out[MAX_EDGES + pos] = (float)(l - 97); pos++; }
    if (m & 2u) { out[pos] = fl; out[MAX_EDGES + pos] = (float)(l - 95); pos++; }
    if (m & 4u) { out[pos] = fl; out[MAX_EDGES + pos] = (float)(l + 95); pos++; }
    if (m & 8u) { out[pos] = fl; out[MAX_EDGES + pos] = (float)(l + 97); pos++; }
}

// --------------------------------------------------------------------------
extern "C" void kernel_launch(void* const* d_in, const int* in_sizes, int n_in,
                              void* d_out, int out_size) {
    // Resolve inputs by element count (unique per input):
    //   d_coarse = 36864 (f32), noise = 9216 (f32),
    //   dropout_mask = 84934656 (bool materialized as 4-byte 0/1 words),
    //   R_scale = 1 (unused)
    const float*        dc    = nullptr;
    const float*        noise = nullptr;
    const unsigned int* mask  = nullptr;

    for (int i = 0; i < n_in; i++) {
        int s = in_sizes[i];
        if (s == MASK_ELEMS) mask  = (const unsigned int*)d_in[i];
        else if (s == 36864) dc    = (const float*)d_in[i];
        else if (s == 9216)  noise = (const float*)d_in[i];
    }

    float* out = (float*)d_out;   // [2, 36864] compared as float32

    k_fused<<<NBLK, 256>>>(dc, noise, mask, out);
}

// round 13
// speedup vs baseline: 1.2330x; 1.0036x over previous
#include <cuda_runtime.h>

// Problem constants
#define GRID_M     96
#define NUM_NODES  9216          // 96*96
#define MAX_EDGES  36864         // 4*NUM_NODES
#define IMG_W      192
#define MASK_ELEMS 84934656      // 9216*9216
#define NBLK       36            // 9216 / 256 blocks; all co-resident (<=148 SMs)

typedef unsigned long long u64;

// Scratch (no allocations, no resets needed):
// g_gen: monotonic; all 36 blocks of one call see the same gen = ticket/36.
// Publications are single 64-bit words ((gen+1)<<32 | payload): the generation
// tag makes stale values self-identifying, so no fences and no reset.
__device__ unsigned int g_gen;        // init 0
__device__ u64 g_pub_min[NBLK];       // (gen+1)<<32 | float_bits(block min)
__device__ u64 g_pub_max[NBLK];       // (gen+1)<<32 | float_bits(block max)
__device__ u64 g_pub_cnt[NBLK];       // (gen+1)<<32 | block edge count

// pool+noise value of node (i,j): bit-identical everywhere (same op order).
__device__ __forceinline__ float node_d(const float* __restrict__ dc,
                                        const float* __restrict__ noise,
                                        int i, int j) {
    const float2* r0 = reinterpret_cast<const float2*>(dc + (2 * i) * IMG_W);
    const float2* r1 = reinterpret_cast<const float2*>(dc + (2 * i + 1) * IMG_W);
    float2 a = r0[j];
    float2 c = r1[j];
    return fmaxf(fmaxf(a.x, a.y), fmaxf(c.x, c.y)) + noise[i * GRID_M + j];
}

__device__ __forceinline__ u64 vload64(const u64* p) {
    return *((volatile const u64*)p);
}

// --------------------------------------------------------------------------
// Single fused kernel: 36 blocks x 256 threads, one node per thread.
// Two data-carrying flag exchanges (min/max partials, then counts); the poll
// that detects completion simultaneously delivers the payloads.
// --------------------------------------------------------------------------
__global__ __launch_bounds__(256, 1)
void k_fused(const float* __restrict__ dc, const float* __restrict__ noise,
             const unsigned int* __restrict__ mask, float* __restrict__ out) {
    __shared__ float    smn[8], smx[8];
    __shared__ int      sws[8];
    __shared__ float    s_th;
    __shared__ int      s_base;
    __shared__ unsigned s_gen;

    const int b    = blockIdx.x;
    const int t    = threadIdx.x;
    const int lane = t & 31;
    const int w    = t >> 5;
    const int l    = b * 256 + t;          // node id, 0..9215
    const int i    = l / GRID_M;
    const int j    = l - i * GRID_M;

    // ---- per-call generation (same value in all 36 blocks) ----
    if (t == 0) s_gen = atomicAdd(&g_gen, 1u) / NBLK;

    // ---- Issue ALL independent scattered loads up front ----
    const bool up = (i > 0), dn = (i < GRID_M - 1);
    const bool lt = (j > 0), rt = (j < GRID_M - 1);
    const unsigned rowbase = (unsigned)l * (unsigned)NUM_NODES;

    unsigned mk0 = 0, mk1 = 0, mk2 = 0, mk3 = 0;   // dropout words (0/1)
    if (up && lt) mk0 = mask[rowbase + (unsigned)(l - 97)];
    if (up && rt) mk1 = mask[rowbase + (unsigned)(l - 95)];
    if (dn && lt) mk2 = mask[rowbase + (unsigned)(l + 95)];
    if (dn && rt) mk3 = mask[rowbase + (unsigned)(l + 97)];

    // own pooled value (pre-noise) + d
    float v;
    {
        const float2* r0 = reinterpret_cast<const float2*>(dc + (2 * i) * IMG_W);
        const float2* r1 = reinterpret_cast<const float2*>(dc + (2 * i + 1) * IMG_W);
        float2 a = r0[j];
        float2 c = r1[j];
        v = fmaxf(fmaxf(a.x, a.y), fmaxf(c.x, c.y));
    }
    const float dv = v + noise[l];

    // neighbor d values (bit-identical recomputation)
    float n0 = 0.f, n1 = 0.f, n2 = 0.f, n3 = 0.f;
    if (up && lt) n0 = node_d(dc, noise, i - 1, j - 1);
    if (up && rt) n1 = node_d(dc, noise, i - 1, j + 1);
    if (dn && lt) n2 = node_d(dc, noise, i + 1, j - 1);
    if (dn && rt) n3 = node_d(dc, noise, i + 1, j + 1);

    // ---- Sentinel fill (73728 floats = 2 x float4 per thread) ----
    {
        float4 s4 = make_float4((float)NUM_NODES, (float)NUM_NODES,
                                (float)NUM_NODES, (float)NUM_NODES);
        float4* o4 = reinterpret_cast<float4*>(out);
        o4[l]             = s4;
        o4[l + NUM_NODES] = s4;
    }

    // ---- Block min/max over own 256 pooled values ----
    {
        float mn = v, mx = v;
#pragma unroll
        for (int o = 16; o; o >>= 1) {
            mn = fminf(mn, __shfl_xor_sync(0xffffffffu, mn, o));
            mx = fmaxf(mx, __shfl_xor_sync(0xffffffffu, mx, o));
        }
        if (lane == 0) { smn[w] = mn; smx[w] = mx; }
    }
    __syncthreads();                       // also publishes s_gen

    const unsigned gen = s_gen;
    const u64 tag = ((u64)(gen + 1)) << 32;

    // thread 0: fold 8 warp partials, publish tagged min/max (single words)
    if (t == 0) {
        float mn = smn[0], mx = smx[0];
#pragma unroll
        for (int k = 1; k < 8; k++) {
            mn = fminf(mn, smn[k]);
            mx = fmaxf(mx, smx[k]);
        }
        g_pub_min[b] = tag | (u64)(unsigned)__float_as_int(mn);
        g_pub_max[b] = tag | (u64)(unsigned)__float_as_int(mx);
    }

    // warp 0 polls all 36 min/max pairs; payload arrives with the poll
    if (w == 0) {
        const int e2 = lane + 32;          // lanes 0..3 own a second entry
        u64 a0, a1, b0 = tag, b1 = tag;
        for (;;) {
            a0 = vload64(&g_pub_min[lane]);
            a1 = vload64(&g_pub_max[lane]);
            bool ok = (a0 >= tag) & (a1 >= tag);
            if (e2 < NBLK) {
                b0 = vload64(&g_pub_min[e2]);
                b1 = vload64(&g_pub_max[e2]);
                ok &= (b0 >= tag) & (b1 >= tag);
            }
            if (__all_sync(0xffffffffu, ok)) break;
        }
        float mn = __int_as_float((int)(unsigned)a0);
        float mx = __int_as_float((int)(unsigned)a1);
        if (e2 < NBLK) {
            mn = fminf(mn, __int_as_float((int)(unsigned)b0));
            mx = fmaxf(mx, __int_as_float((int)(unsigned)b1));
        }
#pragma unroll
        for (int o = 16; o; o >>= 1) {
            mn = fminf(mn, __shfl_xor_sync(0xffffffffu, mn, o));
            mx = fmaxf(mx, __shfl_xor_sync(0xffffffffu, mx, o));
        }
        if (lane == 0) s_th = (mx - mn) / 96.0f;  // exact f32 order as reference
    }
    __syncthreads();
    const float th = s_th;

    // ---- Edge tests (all operands already in registers) ----
    unsigned m = 0;
    if (mk0 && fabsf(n0 - dv) <= th) m |= 1u;   // (i-1,j-1)
    if (mk1 && fabsf(n1 - dv) <= th) m |= 2u;   // (i-1,j+1)
    if (mk2 && fabsf(n2 - dv) <= th) m |= 4u;   // (i+1,j-1)
    if (mk3 && fabsf(n3 - dv) <= th) m |= 8u;   // (i+1,j+1)

    // ---- Block exclusive scan + total ----
    const int c = __popc(m);
    int incl = c;
#pragma unroll
    for (int o = 1; o < 32; o <<= 1) {
        int u = __shfl_up_sync(0xffffffffu, incl, o);
        if (lane >= o) incl += u;
    }
    if (lane == 31) sws[w] = incl;
    __syncthreads();
    int wbase = 0, total = 0;
#pragma unroll
    for (int k = 0; k < 8; k++) {
        int sv = sws[k];
        wbase += (k < w) ? sv : 0;
        total += sv;
    }
    const int excl = wbase + (incl - c);

    // ---- Publish tagged count; warp 0 polls all 36 and prefixes them ----
    if (t == 0) g_pub_cnt[b] = tag | (u64)(unsigned)total;

    if (w == 0) {
        const int e2 = lane + 32;
        u64 a0, b0 = tag;
        for (;;) {
            a0 = vload64(&g_pub_cnt[lane]);
            bool ok = (a0 >= tag);
            if (e2 < NBLK) {
                b0 = vload64(&g_pub_cnt[e2]);
                ok &= (b0 >= tag);
            }
            if (__all_sync(0xffffffffu, ok)) break;
        }
        int s = (lane < b) ? (int)(unsigned)a0 : 0;
        if (e2 < b) s += (int)(unsigned)b0;
#pragma unroll
        for (int o = 16; o; o >>= 1) s += __shfl_xor_sync(0xffffffffu, s, o);
        if (lane == 0) s_base = s;
    }
    __syncthreads();

    // ---- Scatter (jnp.nonzero order) over pre-written sentinels ----
    int pos = s_base + excl;
    const float fl = (float)l;
    if (m & 1u) { out[pos] = fl; out[MAX_EDGES + pos] = (float)(l - 97); pos++; }
    if (m & 2u) { out[pos] = fl; out[MAX_EDGES + pos] = (float)(l - 95); pos++; }
    if (m & 4u) { out[pos] = fl; out[MAX_EDGES + pos] = (float)(l + 95); pos++; }
    if (m & 8u) { out[pos] = fl; out[MAX_EDGES + pos] = (float)(l + 97); pos++; }
}

// --------------------------------------------------------------------------
extern "C" void kernel_launch(void* const* d_in, const int* in_sizes, int n_in,
                              void* d_out, int out_size) {
    // Resolve inputs by element count (unique per input):
    //   d_coarse = 36864 (f32), noise = 9216 (f32),
    //   dropout_mask = 84934656 (bool materialized as 4-byte 0/1 words),
    //   R_scale = 1 (unused)
    const float*        dc    = nullptr;
    const float*        noise = nullptr;
    const unsigned int* mask  = nullptr;

    for (int i = 0; i < n_in; i++) {
        int s = in_sizes[i];
        if (s == MASK_ELEMS) mask  = (const unsigned int*)d_in[i];
        else if (s == 36864) dc    = (const float*)d_in[i];
        else if (s == 9216)  noise = (const float*)d_in[i];
    }

    float* out = (float*)d_out;   // [2, 36864] compared as float32

    k_fused<<<NBLK, 256>>>(dc, noise, mask, out);
}